// round 15
// baseline (speedup 1.0000x reference)
#include <cuda_runtime.h>
#include <math.h>
#include <stdint.h>

#define T_   512
#define B_   128
#define E_   128
#define HD_  128
#define G4_  512   // 4*HD
#define K_   9
#define V_   50000

typedef unsigned long long ull;

// ---------------- f32x2 packed-math helpers (PTX-only on sm_103a) -------------
__device__ __forceinline__ void fma2(ull& d, ull a, ull b) {
    asm("fma.rn.f32x2 %0, %1, %2, %0;" : "+l"(d) : "l"(a), "l"(b));
}
__device__ __forceinline__ ull dup2(float x) {
    ull r;
    asm("mov.b64 %0, {%1, %1};" : "=l"(r) : "f"(x));
    return r;
}
__device__ __forceinline__ ull pack2(float lo, float hi) {
    ull r;
    asm("mov.b64 %0, {%1, %2};" : "=l"(r) : "f"(lo), "f"(hi));
    return r;
}
__device__ __forceinline__ float2 unpack2(ull v) {
    float2 f;
    asm("mov.b64 {%0, %1}, %2;" : "=f"(f.x), "=f"(f.y) : "l"(v));
    return f;
}

// ---------------- scratch (device globals; no runtime allocation) -------------
__device__ float g_Xf[(size_t)T_ * B_ * G4_];   // [t][b][512] fwd input proj + bias
__device__ float g_Xb[(size_t)T_ * B_ * G4_];   // backward
__device__ float g_H [(size_t)T_ * B_ * 256];   // [t][b][256] concat hidden
__device__ float g_emis[(size_t)B_ * T_ * K_];  // [b][t][k]

// tiny no-op spacers: keep lstm on the 4th launch slot (ncu captures launch #4)
__global__ void nop_kernel() {}

// ---------------- kernel A: embed gather + input projection GEMM --------------
__global__ void __launch_bounds__(256) proj_kernel(
                            const int* __restrict__ x, const float* __restrict__ emb,
                            const float* __restrict__ w_f, const float* __restrict__ w_b,
                            const float* __restrict__ bihf, const float* __restrict__ bhhf,
                            const float* __restrict__ bihb, const float* __restrict__ bhhb)
{
    __shared__ float As[64][72];      // [k][row], 72-pad keeps 16B row alignment
    __shared__ float Bs[64][72];      // [k][col]
    __shared__ float bias_s[64];
    __shared__ int   tok_s[64];

    const int tid = threadIdx.x;
    const int m0 = blockIdx.y * 64;
    const int n0 = blockIdx.x * 64;           // 0..1023
    const int dir = n0 >> 9;
    const int gbase = n0 & 511;
    const float* w  = dir ? w_b  : w_f;
    const float* bi = dir ? bihb : bihf;
    const float* bh = dir ? bhhb : bhhf;

    if (tid < 64) {
        int m = m0 + tid;
        int t = m >> 7, b = m & 127;
        int tok = x[b * T_ + t];
        if ((unsigned)tok >= (unsigned)V_) tok = 0;   // safety clamp
        tok_s[tid] = tok;
        int grow = gbase + tid;
        bias_s[tid] = bi[grow] + bh[grow];
    }
    __syncthreads();

    const int tx = tid & 15, ty = tid >> 4;
    ull acc[4][2];
#pragma unroll
    for (int i = 0; i < 4; i++) { acc[i][0] = 0ull; acc[i][1] = 0ull; }

    for (int kc = 0; kc < 128; kc += 64) {
        for (int idx = tid; idx < 4096; idx += 256) {
            int row = idx >> 6, kk = idx & 63;
            As[kk][row] = emb[(size_t)tok_s[row] * E_ + kc + kk];
            Bs[kk][row] = w[(size_t)(gbase + row) * E_ + kc + kk];
        }
        __syncthreads();

#pragma unroll 8
        for (int k = 0; k < 64; k++) {
            float4     av = *(const float4*)&As[k][ty * 4];
            ulonglong2 bv = *(const ulonglong2*)&Bs[k][tx * 4];
            ull a0 = dup2(av.x), a1 = dup2(av.y), a2 = dup2(av.z), a3 = dup2(av.w);
            fma2(acc[0][0], a0, bv.x); fma2(acc[0][1], a0, bv.y);
            fma2(acc[1][0], a1, bv.x); fma2(acc[1][1], a1, bv.y);
            fma2(acc[2][0], a2, bv.x); fma2(acc[2][1], a2, bv.y);
            fma2(acc[3][0], a3, bv.x); fma2(acc[3][1], a3, bv.y);
        }
        __syncthreads();
    }

    float* X = dir ? g_Xb : g_Xf;
    const int col = tx * 4;
#pragma unroll
    for (int i = 0; i < 4; i++) {
        int m = m0 + ty * 4 + i;
        float2 c01 = unpack2(acc[i][0]);
        float2 c23 = unpack2(acc[i][1]);
        float4 o = make_float4(c01.x + bias_s[col + 0], c01.y + bias_s[col + 1],
                               c23.x + bias_s[col + 2], c23.y + bias_s[col + 3]);
        *(float4*)&X[(size_t)m * G4_ + gbase + col] = o;
    }
}

// ---------------- kernel B: cluster-of-2 LSTM, k-pair packed, 1-bar step ------
// 128 CTAs = 64 clusters of 2. CTA: 512 threads = 256 gate rows x 2 k-halves.
// W pre-packed as f32x2 (k even/odd pairs) -> no dup-mov in the inner loop.
// h buffer stores (h_{2k}, h_{2k+1}) pairs per batch. Gates double-buffered by
// parity; per-act-thread mbarrier release-arrives (count 512) replace the
// trailing __syncthreads, letting the kh=1 warps run ahead into the next wait.
__global__ void __cluster_dims__(2, 1, 1) __launch_bounds__(512, 1)
lstm_kernel(const float* __restrict__ whhf, const float* __restrict__ whhb)
{
    // hkb2[p][kp*8 + b*2 + (k&1)] : k-pair interleaved per batch, 4KB total
    __shared__ __align__(16) float hkb2[2][64 * 8];
    __shared__ float gq[2][2][4][256];               // [parity][khalf][b][row] 16KB
    __shared__ __align__(8) unsigned long long mbar[2];

    const int tid = threadIdx.x;                      // 512 threads
    uint32_t rank;
    asm("mov.u32 %0, %%cluster_ctarank;" : "=r"(rank));
    const int cid = blockIdx.x >> 1;                  // 0..63
    const int dir = cid >> 5;
    const int b0  = (cid & 31) * 4;

    const float* Xin = dir ? g_Xb : g_Xf;
    const float* whh = dir ? whhb : whhf;

    // GEMM role: local row r (0..255) = gate<<6 | unit-in-half, k-half
    const int r    = tid & 255;
    const int half = tid >> 8;
    const int grow = (r >> 6) * 128 + (int)rank * 64 + (r & 63);

    // W k-half pre-packed as 32 f32x2 pairs (k even/odd)
    ull wpk[32];
#pragma unroll
    for (int j = 0; j < 32; j += 2) {
        float4 v = *(const float4*)&whh[(size_t)grow * HD_ + half * 64 + 2 * j];
        wpk[j]     = pack2(v.x, v.y);
        wpk[j + 1] = pack2(v.z, v.w);
    }

    // ACT role (threads 0..255): batch (0..3), unit-in-half ul (0..63)
    const int bact = tid >> 6, ul = tid & 63;
    const int ug = (int)rank * 64 + ul;               // global unit 0..127
    const bool is_act = (tid < 256);

    if (tid == 0) {
        uint32_t mb = (uint32_t)__cvta_generic_to_shared(&mbar[0]);
        asm volatile("mbarrier.init.shared.b64 [%0], 512;" :: "r"(mb) : "memory");
        asm volatile("mbarrier.init.shared.b64 [%0], 512;" :: "r"(mb + 8) : "memory");
    }
    for (int i = tid; i < 64 * 8; i += 512) hkb2[0][i] = 0.f;
    float c = 0.f;
    int ph0 = 0, ph1 = 0;
    __syncthreads();
    // cluster rally: all mbarriers initialized before any remote arrive
    asm volatile("barrier.cluster.arrive.aligned;" ::: "memory");
    asm volatile("barrier.cluster.wait.aligned;"   ::: "memory");

    const uint32_t mb_base = (uint32_t)__cvta_generic_to_shared(&mbar[0]);
    // my h element's slot in the pair-interleaved layout (per parity)
    const uint32_t h_off0 = is_act
        ? (uint32_t)__cvta_generic_to_shared(&hkb2[0][(ug >> 1) * 8 + bact * 2 + (ug & 1)])
        : 0u;

    for (int s = 0; s < T_; s++) {
        const int t = dir ? (T_ - 1 - s) : s;
        const int p = s & 1;

        // X prefetch BEFORE the wait (global, h-independent -> overlaps sync)
        float x0 = 0.f, x1 = 0.f, x2 = 0.f, x3 = 0.f;
        if (is_act) {
            const float* Xr = &Xin[(size_t)t * B_ * G4_ + (size_t)(b0 + bact) * G4_];
            x0 = Xr[ug]; x1 = Xr[128 + ug]; x2 = Xr[256 + ug]; x3 = Xr[384 + ug];
        }

        // wait until h buffer p is full in MY smem (acquire, cluster scope)
        if (s > 0) {
            const uint32_t mb = mb_base + (uint32_t)p * 8u;
            const int par = p ? ph1 : ph0;
            uint32_t done;
            asm volatile(
                "{\n\t.reg .pred pr;\n\t"
                "mbarrier.try_wait.parity.acquire.cluster.shared::cta.b64 pr, [%1], %2;\n\t"
                "selp.b32 %0, 1, 0, pr;\n\t}"
                : "=r"(done) : "r"(mb), "r"(par) : "memory");
            if (!done) {
                asm volatile(
                    "{\n\t.reg .pred P1;\n\t"
                    "WL_%=:\n\t"
                    "mbarrier.try_wait.parity.acquire.cluster.shared::cta.b64 P1, [%0], %1, 0x989680;\n\t"
                    "@P1 bra.uni WD_%=;\n\t"
                    "bra.uni WL_%=;\n\t"
                    "WD_%=:\n\t}"
                    :: "r"(mb), "r"(par) : "memory");
            }
            if (p) ph1 ^= 1; else ph0 ^= 1;
        }

        // GEMM partial over my k-half: even/odd-k packed accumulation
        const float* hk = hkb2[p];
        ull a0 = 0ull, a1 = 0ull, a2 = 0ull, a3 = 0ull;
#pragma unroll
        for (int kp = 0; kp < 32; kp++) {
            const int base = (half * 32 + kp) * 8;
            ulonglong2 h01 = *(const ulonglong2*)&hk[base];
            ulonglong2 h23 = *(const ulonglong2*)&hk[base + 4];
            ull wd = wpk[kp];
            fma2(a0, wd, h01.x);
            fma2(a1, wd, h01.y);
            fma2(a2, wd, h23.x);
            fma2(a3, wd, h23.y);
        }
        {
            float2 s0 = unpack2(a0), s1 = unpack2(a1);
            float2 s2 = unpack2(a2), s3 = unpack2(a3);
            gq[p][half][0][r] = s0.x + s0.y;
            gq[p][half][1][r] = s1.x + s1.y;
            gq[p][half][2][r] = s2.x + s2.y;
            gq[p][half][3][r] = s3.x + s3.y;
        }
        __syncthreads();   // gq[p] complete before act reads it

        // activation + h stores + per-thread release-arrives (no trailing bar)
        if (is_act) {
            float pi = gq[p][0][bact][ul]       + gq[p][1][bact][ul]       + x0;
            float pf = gq[p][0][bact][64 + ul]  + gq[p][1][bact][64 + ul]  + x1;
            float pg = gq[p][0][bact][128 + ul] + gq[p][1][bact][128 + ul] + x2;
            float po = gq[p][0][bact][192 + ul] + gq[p][1][bact][192 + ul] + x3;
            float ig = 1.f / (1.f + expf(-pi));
            float fg = 1.f / (1.f + expf(-pf));
            float gg = tanhf(pg);
            float og = 1.f / (1.f + expf(-po));
            c = fg * c + ig * gg;
            float h = og * tanhf(c);

            if (s < T_ - 1) {
                const uint32_t off = h_off0 + (uint32_t)((s + 1) & 1) * (64 * 8 * 4);
                const uint32_t mbo = mb_base + (uint32_t)((s + 1) & 1) * 8u;
#pragma unroll
                for (int ctac = 0; ctac < 2; ctac++) {
                    uint32_t rem;
                    asm("mapa.shared::cluster.u32 %0, %1, %2;" : "=r"(rem) : "r"(off), "r"(ctac));
                    asm volatile("st.shared::cluster.f32 [%0], %1;" :: "r"(rem), "f"(h) : "memory");
                }
                g_H[(size_t)t * B_ * 256 + (size_t)(b0 + bact) * 256 + dir * 128 + ug] = h;
#pragma unroll
                for (int ctac = 0; ctac < 2; ctac++) {
                    uint32_t rem;
                    asm("mapa.shared::cluster.u32 %0, %1, %2;" : "=r"(rem) : "r"(mbo), "r"(ctac));
                    asm volatile("mbarrier.arrive.release.cluster.shared::cluster.b64 _, [%0];"
                                 :: "r"(rem) : "memory");
                }
            } else {
                g_H[(size_t)t * B_ * 256 + (size_t)(b0 + bact) * 256 + dir * 128 + ug] = h;
            }
        }
        // gemm-only warps (tid>=256) fall through directly to the next wait
    }

    // final rally: no CTA exits while its peer might still touch its SMEM
    asm volatile("barrier.cluster.arrive.aligned;" ::: "memory");
    asm volatile("barrier.cluster.wait.aligned;"   ::: "memory");
}

// ---------------- kernel C: emissions = H @ W_tag.T + b_tag -------------------
__global__ void emis_kernel(const float* __restrict__ W_tag, const float* __restrict__ b_tag)
{
    __shared__ float Ws[K_ * 256];
    __shared__ float bs[K_];
    const int tid = threadIdx.x;
    for (int i = tid; i < K_ * 256; i += 256) Ws[i] = W_tag[i];
    if (tid < K_) bs[tid] = b_tag[tid];
    __syncthreads();

    const int warp = tid >> 5, lane = tid & 31;
    const int rr = blockIdx.x * 8 + warp;          // row in [t*128+b]
    const float* hrow = &g_H[(size_t)rr * 256];
    float hv[8];
#pragma unroll
    for (int i = 0; i < 8; i++) hv[i] = hrow[lane + 32 * i];
    const int t = rr >> 7, b = rr & 127;
#pragma unroll
    for (int k = 0; k < K_; k++) {
        float s = 0.f;
#pragma unroll
        for (int i = 0; i < 8; i++) s += hv[i] * Ws[k * 256 + lane + 32 * i];
#pragma unroll
        for (int off = 16; off > 0; off >>= 1) s += __shfl_down_sync(0xffffffffu, s, off);
        if (lane == 0) g_emis[(size_t)b * T_ * K_ + t * K_ + k] = s + bs[k];
    }
}

// ---------------- kernel D: CRF Viterbi — SMEM-staged emissions ---------------
__global__ void __launch_bounds__(64) viterbi_kernel(
                               const float* __restrict__ start_t, const float* __restrict__ end_t,
                               const float* __restrict__ trans, float* __restrict__ out)
{
    __shared__ float em_s[2][T_ * K_];          // 36864 B
    __shared__ unsigned char bp[2][T_ * K_];    //  9216 B
    const int tid = threadIdx.x, warp = tid >> 5, lane = tid & 31;
    const int b = blockIdx.x * 2 + warp;

    {
        const float4* src = (const float4*)&g_emis[(size_t)b * T_ * K_];
        float4* dst = (float4*)em_s[warp];
        for (int i = lane; i < (T_ * K_) / 4; i += 32) dst[i] = src[i];
    }
    __syncwarp();

    const float* em = em_s[warp];
    const bool act = (lane < K_);

    float tr[K_];
    float score;
    if (act) {
#pragma unroll
        for (int i = 0; i < K_; i++) tr[i] = trans[i * K_ + lane];
        score = start_t[lane] + em[lane];
    } else {
#pragma unroll
        for (int i = 0; i < K_; i++) tr[i] = 0.f;
        score = -3.0e38f;
    }
    __syncwarp();

    for (int t = 1; t < T_; t++) {
        float em_t = act ? em[t * K_ + lane] : 0.f;
        float m = -3.0e38f; int arg = 0;
#pragma unroll
        for (int i = 0; i < K_; i++) {
            float si = __shfl_sync(0xffffffffu, score, i);
            float v = si + tr[i];
            if (v > m) { m = v; arg = i; }   // strict > keeps first max (jnp.argmax)
        }
        if (act) {
            bp[warp][t * K_ + lane] = (unsigned char)arg;
            score = m + em_t;
        }
    }
    if (act) score += end_t[lane];

    int best = 0; float bm = -3.0e38f;
#pragma unroll
    for (int jj = 0; jj < K_; jj++) {
        float sj = __shfl_sync(0xffffffffu, score, jj);
        if (sj > bm) { bm = sj; best = jj; }
    }
    __syncwarp();
    if (lane == 0) {
        int tag = best;
        out[b * T_ + (T_ - 1)] = (float)tag;
        for (int t = T_ - 2; t >= 0; t--) {
            tag = bp[warp][(t + 1) * K_ + tag];
            out[b * T_ + t] = (float)tag;
        }
    }
}

// ---------------- launch -------------------------------------------------------
extern "C" void kernel_launch(void* const* d_in, const int* in_sizes, int n_in,
                              void* d_out, int out_size)
{
    const int*   x      = (const int*)  d_in[0];
    const float* emb    = (const float*)d_in[1];
    const float* w_ih_f = (const float*)d_in[2];
    const float* w_hh_f = (const float*)d_in[3];
    const float* b_ih_f = (const float*)d_in[4];
    const float* b_hh_f = (const float*)d_in[5];
    const float* w_ih_b = (const float*)d_in[6];
    const float* w_hh_b = (const float*)d_in[7];
    const float* b_ih_b = (const float*)d_in[8];
    const float* b_hh_b = (const float*)d_in[9];
    const float* W_tag  = (const float*)d_in[10];
    const float* b_tag  = (const float*)d_in[11];
    const float* start_t= (const float*)d_in[12];
    const float* end_t  = (const float*)d_in[13];
    const float* trans  = (const float*)d_in[14];
    float* out = (float*)d_out;

    proj_kernel<<<dim3(16, 1024), 256>>>(x, emb, w_ih_f, w_ih_b,
                                         b_ih_f, b_hh_f, b_ih_b, b_hh_b);
    nop_kernel<<<1, 32>>>();                       // spacer: lstm -> launch #4
    nop_kernel<<<1, 32>>>();                       // (ncu captures launch #4)
    lstm_kernel<<<128, 512>>>(w_hh_f, w_hh_b);
    emis_kernel<<<8192, 256>>>(W_tag, b_tag);
    viterbi_kernel<<<64, 64>>>(start_t, end_t, trans, out);
}